// round 5
// baseline (speedup 1.0000x reference)
#include <cuda_runtime.h>
#include <math_constants.h>

// Problem constants
#define BB 2
#define TT 4096
#define EE 768
#define HH 12
#define SS 64            // head dim
#define WW 256           // one-sided window
#define MM (BB*TT)       // 8192 rows in projection GEMM

// Scratch for projections, head-major layout [B, H, T, S]
__device__ float g_q[BB*HH*TT*SS];
__device__ float g_k[BB*HH*TT*SS];
__device__ float g_v[BB*HH*TT*SS];

// ---------------------------------------------------------------------------
// Kernel 1: QKV projection GEMM.  y = x @ W^T   (y[m,n] = sum_k x[m,k]*W[n,k])
// Tile: BM=64, BN=64, BK=16, 256 threads, 4x4 micro-tile per thread.
// blockIdx.z in {0,1,2} selects (Wq->g_q scaled, Wk->g_k, Wv->g_v).
// BN=64 == head size, so blockIdx.y IS the head index -> coalesced head-major
// writes.
// ---------------------------------------------------------------------------
__global__ __launch_bounds__(256) void qkv_gemm(
    const float* __restrict__ x,
    const float* __restrict__ Wq,
    const float* __restrict__ Wk,
    const float* __restrict__ Wv)
{
    const int z = blockIdx.z;
    const float* __restrict__ W = (z == 0) ? Wq : (z == 1) ? Wk : Wv;
    float* __restrict__ outp     = (z == 0) ? g_q : (z == 1) ? g_k : g_v;
    const float scale = (z == 0) ? 0.125f : 1.0f;   // 1/sqrt(64) on Q

    // +2 padding: store pattern Xs[c][r] is conflict-free (stride 66 -> banks
    // (2c+r)%32, even/odd disjoint for the two row-groups of a warp).
    __shared__ float Xs[16][66];
    __shared__ float Ws[16][66];

    const int tid = threadIdx.x;
    const int tx = tid & 15;        // 0..15 -> output column group
    const int ty = tid >> 4;        // 0..15 -> output row group
    const int m0 = blockIdx.x * 64;
    const int n0 = blockIdx.y * 64;
    const int h  = blockIdx.y;      // head index (BN == SS)

    float acc[4][4];
#pragma unroll
    for (int i = 0; i < 4; i++)
#pragma unroll
        for (int j = 0; j < 4; j++) acc[i][j] = 0.0f;

    for (int k0 = 0; k0 < EE; k0 += 16) {
        // cooperative load of x tile (64x16) and W tile (64x16), transposed
#pragma unroll
        for (int ii = 0; ii < 4; ii++) {
            int e = tid + 256 * ii;
            int r = e >> 4;         // 0..63
            int c = e & 15;         // 0..15
            Xs[c][r] = x[(m0 + r) * EE + (k0 + c)];
            Ws[c][r] = W[(n0 + r) * EE + (k0 + c)];
        }
        __syncthreads();

#pragma unroll
        for (int k = 0; k < 16; k++) {
            float a[4], bb[4];
#pragma unroll
            for (int i = 0; i < 4; i++) a[i]  = Xs[k][ty + 16 * i];
#pragma unroll
            for (int j = 0; j < 4; j++) bb[j] = Ws[k][tx + 16 * j];
#pragma unroll
            for (int i = 0; i < 4; i++)
#pragma unroll
                for (int j = 0; j < 4; j++)
                    acc[i][j] = fmaf(a[i], bb[j], acc[i][j]);
        }
        __syncthreads();
    }

    // write to head-major [B,H,T,S]
#pragma unroll
    for (int i = 0; i < 4; i++) {
        int m = m0 + ty + 16 * i;
        int b = m >> 12;            // m / TT  (TT = 4096)
        int t = m & (TT - 1);
        float* rowp = outp + (((b * HH + h) * TT) + t) * SS;
#pragma unroll
        for (int j = 0; j < 4; j++) {
            rowp[tx + 16 * j] = acc[i][j] * scale;
        }
    }
}

// ---------------------------------------------------------------------------
// Kernel 2: banded (sliding-window) attention with online softmax.
// One thread = one query. CTA = 256 queries of one (b,h) plane.
// K/V streamed through smem in 16-key chunks covering [t0-WW, t0+255+WW].
// Per-thread band: keys j in [max(0,t-WW), min(T-1,t+WW)].
// ---------------------------------------------------------------------------
#define CK 16
#define NCHUNK ((2*WW + 256)/CK)    // 48

__global__ __launch_bounds__(256, 1) void banded_attn(float* __restrict__ out)
{
    const int tid = threadIdx.x;
    const int t0  = blockIdx.x * 256;
    const int h   = blockIdx.y;
    const int b   = blockIdx.z;
    const int t   = t0 + tid;

    const int plane = (b * HH + h) * TT;
    const float4* __restrict__ qp    = (const float4*)(g_q + (plane + t) * SS);
    const float4* __restrict__ kbase = (const float4*)(g_k + (long long)plane * SS);
    const float4* __restrict__ vbase = (const float4*)(g_v + (long long)plane * SS);

    float4 q4[16], o4[16];
#pragma unroll
    for (int i = 0; i < 16; i++) {
        q4[i] = qp[i];
        o4[i] = make_float4(0.f, 0.f, 0.f, 0.f);
    }

    float mrun = -CUDART_INF_F;
    float lrun = 0.0f;
    const int lo = (t - WW) > 0 ? (t - WW) : 0;
    const int hi = (t + WW) < (TT - 1) ? (t + WW) : (TT - 1);

    __shared__ float4 Ks[CK][16];
    __shared__ float4 Vs[CK][16];

    for (int c = 0; c < NCHUNK; c++) {
        const int j0 = t0 - WW + c * CK;
        if (j0 + CK <= 0 || j0 >= TT) continue;   // block-uniform skip

        // cooperative load: CK*16 float4 slots == 256 threads -> 1 each per array
        {
            int r  = tid >> 4;
            int cc = tid & 15;
            int j  = j0 + r;
            bool v = (j >= 0) && (j < TT);
            float4 zero = make_float4(0.f, 0.f, 0.f, 0.f);
            Ks[r][cc] = v ? kbase[j * 16 + cc] : zero;
            Vs[r][cc] = v ? vbase[j * 16 + cc] : zero;
        }
        __syncthreads();

        // per-thread: does this chunk overlap my band?
        if (j0 <= t + WW && j0 + (CK - 1) >= t - WW) {
            float s[CK];
            float cmax = -CUDART_INF_F;
#pragma unroll
            for (int jj = 0; jj < CK; jj++) {
                int j = j0 + jj;
                float4 a = make_float4(0.f, 0.f, 0.f, 0.f);
#pragma unroll
                for (int d = 0; d < 16; d++) {
                    float4 kk = Ks[jj][d];          // warp-broadcast
                    a.x = fmaf(q4[d].x, kk.x, a.x);
                    a.y = fmaf(q4[d].y, kk.y, a.y);
                    a.z = fmaf(q4[d].z, kk.z, a.z);
                    a.w = fmaf(q4[d].w, kk.w, a.w);
                }
                float sv = (a.x + a.y) + (a.z + a.w);
                s[jj] = (j >= lo && j <= hi) ? sv : -CUDART_INF_F;
                cmax  = fmaxf(cmax, s[jj]);
            }

            if (cmax > -CUDART_INF_F) {             // at least one valid key
                float mnew  = fmaxf(mrun, cmax);
                float alpha = __expf(mrun - mnew);  // mrun=-inf -> alpha=0
                lrun *= alpha;
#pragma unroll
                for (int d = 0; d < 16; d++) {
                    o4[d].x *= alpha; o4[d].y *= alpha;
                    o4[d].z *= alpha; o4[d].w *= alpha;
                }
#pragma unroll
                for (int jj = 0; jj < CK; jj++) {
                    float p = __expf(s[jj] - mnew); // masked -> exp(-inf)=0
                    lrun += p;
#pragma unroll
                    for (int d = 0; d < 16; d++) {
                        float4 vv = Vs[jj][d];      // warp-broadcast
                        o4[d].x = fmaf(p, vv.x, o4[d].x);
                        o4[d].y = fmaf(p, vv.y, o4[d].y);
                        o4[d].z = fmaf(p, vv.z, o4[d].z);
                        o4[d].w = fmaf(p, vv.w, o4[d].w);
                    }
                }
                mrun = mnew;
            }
        }
        __syncthreads();
    }

    const float inv = 1.0f / lrun;  // key t always valid -> lrun > 0
    float4* op = (float4*)(out + (((b * TT + t) * HH) + h) * SS);
#pragma unroll
    for (int i = 0; i < 16; i++) {
        float4 o = o4[i];
        o.x *= inv; o.y *= inv; o.z *= inv; o.w *= inv;
        op[i] = o;
    }
}

// ---------------------------------------------------------------------------
// Launcher (graph-capturable: kernel launches only, no allocs, no syncs)
// ---------------------------------------------------------------------------
extern "C" void kernel_launch(void* const* d_in, const int* in_sizes, int n_in,
                              void* d_out, int out_size)
{
    const float* x  = (const float*)d_in[0];
    const float* Wq = (const float*)d_in[1];
    const float* Wk = (const float*)d_in[2];
    const float* Wv = (const float*)d_in[3];
    float* out = (float*)d_out;

    dim3 g1(MM / 64, EE / 64, 3);   // (128, 12, 3)
    qkv_gemm<<<g1, 256>>>(x, Wq, Wk, Wv);

    dim3 g2(TT / 256, HH, BB);      // (16, 12, 2)
    banded_attn<<<g2, 256>>>(out);
}

// round 12
// speedup vs baseline: 6.3324x; 6.3324x over previous
#include <cuda_runtime.h>
#include <math_constants.h>
#include <cstdint>

// Problem constants
#define BB 2
#define TT 4096
#define EE 768
#define HH 12
#define SS 64            // head dim
#define WW 256           // one-sided window
#define MM (BB*TT)       // 8192 rows in projection GEMM

// Scratch for projections, head-major layout [B, H, T, S], tf32-rounded floats
__device__ float g_q[BB*HH*TT*SS];
__device__ float g_k[BB*HH*TT*SS];
__device__ float g_v[BB*HH*TT*SS];

// ---------------------------------------------------------------------------
// tf32 helpers
// ---------------------------------------------------------------------------
__device__ __forceinline__ uint32_t f2tf32(float f) {
    uint32_t u;
    asm("cvt.rna.tf32.f32 %0, %1;" : "=r"(u) : "f"(f));
    return u;
}
__device__ __forceinline__ float f2tf32f(float f) {
    return __uint_as_float(f2tf32(f));
}

// mma.sync m16n8k8 tf32, row.col, fp32 accumulate (in-place C)
__device__ __forceinline__ void mma_tf32(float* c, const uint32_t* a, const uint32_t* b) {
    asm volatile(
        "mma.sync.aligned.m16n8k8.row.col.f32.tf32.tf32.f32 "
        "{%0,%1,%2,%3}, {%4,%5,%6,%7}, {%8,%9}, {%0,%1,%2,%3};"
        : "+f"(c[0]), "+f"(c[1]), "+f"(c[2]), "+f"(c[3])
        : "r"(a[0]), "r"(a[1]), "r"(a[2]), "r"(a[3]), "r"(b[0]), "r"(b[1]));
}

// Fragment layouts (m16n8k8 tf32):
//  A (16x8):  a0=(r, c)  a1=(r+8, c)  a2=(r, c+4)  a3=(r+8, c+4)   r=lane/4, c=lane%4
//  B (8x8):   b0=(k, n)  b1=(k+4, n)                               k=lane%4, n=lane/4
//  C (16x8):  c0=(r,2c) c1=(r,2c+1) c2=(r+8,2c) c3=(r+8,2c+1)

// ---------------------------------------------------------------------------
// Kernel 1: QKV projection GEMM on tensor cores (tf32).
// y[m,n] = sum_k x[m,k] * W[n,k]   (row.col mma: A=x row-major, B(k,n)=W[n,k])
// BM=128, BN=64(=head), BK=32, 256 threads = 8 warps (4M x 2N), warp tile 32x32.
// Epilogue: scale (Q only), round to tf32, store head-major [B,H,T,S].
// ---------------------------------------------------------------------------
__global__ __launch_bounds__(256) void qkv_gemm_tc(
    const float* __restrict__ x,
    const float* __restrict__ Wq,
    const float* __restrict__ Wk,
    const float* __restrict__ Wv)
{
    const int z = blockIdx.z;
    const float* __restrict__ W = (z == 0) ? Wq : (z == 1) ? Wk : Wv;
    float* __restrict__ outp    = (z == 0) ? g_q : (z == 1) ? g_k : g_v;
    const float scale = (z == 0) ? 0.125f : 1.0f;

    __shared__ float Xs[128][36];   // [m][k], 32 k-cols + pad: frag loads conflict-free
    __shared__ float Ws[64][36];    // [n][k]

    const int tid  = threadIdx.x;
    const int wid  = tid >> 5;
    const int lane = tid & 31;
    const int warpM = wid >> 1;     // 0..3
    const int warpN = wid & 1;      // 0..1
    const int m0 = blockIdx.x * 128;
    const int h  = blockIdx.y;      // head == BN block
    const int n0 = h * 64;

    float acc[2][4][4];
#pragma unroll
    for (int mt = 0; mt < 2; mt++)
#pragma unroll
        for (int nt = 0; nt < 4; nt++)
#pragma unroll
            for (int i = 0; i < 4; i++) acc[mt][nt][i] = 0.0f;

    const int lr = tid >> 3;        // 0..31
    const int lc = tid & 7;         // 0..7  (float4 column within 32-wide tile)

    for (int k0 = 0; k0 < EE; k0 += 32) {
        // stage X tile (128x32) and W tile (64x32), converting to tf32
#pragma unroll
        for (int it = 0; it < 4; it++) {
            int r = lr + 32 * it;
            float4 v = *(const float4*)&x[(m0 + r) * EE + k0 + lc * 4];
            Xs[r][lc*4+0] = f2tf32f(v.x);
            Xs[r][lc*4+1] = f2tf32f(v.y);
            Xs[r][lc*4+2] = f2tf32f(v.z);
            Xs[r][lc*4+3] = f2tf32f(v.w);
        }
#pragma unroll
        for (int it = 0; it < 2; it++) {
            int r = lr + 32 * it;
            float4 v = *(const float4*)&W[(n0 + r) * EE + k0 + lc * 4];
            Ws[r][lc*4+0] = f2tf32f(v.x);
            Ws[r][lc*4+1] = f2tf32f(v.y);
            Ws[r][lc*4+2] = f2tf32f(v.z);
            Ws[r][lc*4+3] = f2tf32f(v.w);
        }
        __syncthreads();

#pragma unroll
        for (int kk = 0; kk < 4; kk++) {
            const int kb = kk * 8 + (lane & 3);
            uint32_t a[2][4];
#pragma unroll
            for (int mt = 0; mt < 2; mt++) {
                int row = warpM * 32 + mt * 16 + (lane >> 2);
                a[mt][0] = __float_as_uint(Xs[row    ][kb    ]);
                a[mt][1] = __float_as_uint(Xs[row + 8][kb    ]);
                a[mt][2] = __float_as_uint(Xs[row    ][kb + 4]);
                a[mt][3] = __float_as_uint(Xs[row + 8][kb + 4]);
            }
            uint32_t b[4][2];
#pragma unroll
            for (int nt = 0; nt < 4; nt++) {
                int col = warpN * 32 + nt * 8 + (lane >> 2);
                b[nt][0] = __float_as_uint(Ws[col][kb    ]);
                b[nt][1] = __float_as_uint(Ws[col][kb + 4]);
            }
#pragma unroll
            for (int mt = 0; mt < 2; mt++)
#pragma unroll
                for (int nt = 0; nt < 4; nt++)
                    mma_tf32(acc[mt][nt], a[mt], b[nt]);
        }
        __syncthreads();
    }

    // epilogue: scale, round to tf32, store head-major [B,H,T,S]
#pragma unroll
    for (int mt = 0; mt < 2; mt++) {
        int m = m0 + warpM * 32 + mt * 16 + (lane >> 2);
#pragma unroll
        for (int half = 0; half < 2; half++) {
            int mm = m + half * 8;
            int bI = mm >> 12;
            int t  = mm & (TT - 1);
            float* rowp = outp + ((bI * HH + h) * TT + t) * SS;
#pragma unroll
            for (int nt = 0; nt < 4; nt++) {
                int col = warpN * 32 + nt * 8 + (lane & 3) * 2;
                float2 o;
                o.x = f2tf32f(acc[mt][nt][half * 2 + 0] * scale);
                o.y = f2tf32f(acc[mt][nt][half * 2 + 1] * scale);
                *(float2*)&rowp[col] = o;
            }
        }
    }
}

// ---------------------------------------------------------------------------
// Kernel 2: banded attention on tensor cores, flash-style online softmax.
// CTA = 128 queries of one (b,h). 8 warps, each owns 16 query rows (one m16).
// Keys streamed in 64-chunks spanning [t0-256, t0+384).
// Q fragments persistent in registers. P is time-multiplexed through a tiny
// per-warp 16x8 buffer (one S n-tile == one PV k-group at a time).
// R10 FIX: K/V tiles are 64 dims wide -> ld must be >= 64 (was 36/40,
// corrupting the tiles). ld=68 (K) / 72 (V) chosen so the B-fragment read
// patterns hit all 32 banks:
//   QK: addr=(key)*68+dim  -> banks 4*qr+qc  (68*8=544 == 0 mod 32)
//   PV: addr=(key)*72+dim  -> banks 8*qc+qr  (72*8=576 == 0 mod 32)
// ---------------------------------------------------------------------------
#define QB 128
#define KC 64
#define NCH ((2*WW + QB)/KC)   // 10

__global__ __launch_bounds__(256, 1) void banded_attn_tc(float* __restrict__ out)
{
    __shared__ float Ks[KC][68];       // [key][dim 0..63]
    __shared__ float Vs[KC][72];       // [key][dim 0..63]
    __shared__ float Pb[8][16][12];    // per-warp P slice [qrow][key-in-group]

    const int tid  = threadIdx.x;
    const int wid  = tid >> 5;
    const int lane = tid & 31;
    const int t0 = blockIdx.x * QB;
    const int h  = blockIdx.y;
    const int b  = blockIdx.z;
    const int plane = (b * HH + h) * TT;

    const int qr = (lane >> 2);             // 0..7
    const int qc = (lane & 3);              // 0..3
    const int tq0 = t0 + wid * 16 + qr;     // this thread's query row 0
    const int tq1 = tq0 + 8;                //                  ... row 1

    // persistent Q fragments (already tf32-rounded & scaled by GEMM epilogue)
    uint32_t qa[8][4];
#pragma unroll
    for (int kk = 0; kk < 8; kk++) {
        const float* q0 = g_q + (plane + tq0) * SS + kk * 8 + qc;
        const float* q1 = g_q + (plane + tq1) * SS + kk * 8 + qc;
        qa[kk][0] = __float_as_uint(q0[0]);
        qa[kk][1] = __float_as_uint(q1[0]);
        qa[kk][2] = __float_as_uint(q0[4]);
        qa[kk][3] = __float_as_uint(q1[4]);
    }

    float oa[8][4];
#pragma unroll
    for (int nt = 0; nt < 8; nt++)
#pragma unroll
        for (int i = 0; i < 4; i++) oa[nt][i] = 0.0f;

    float mr0 = -CUDART_INF_F, mr1 = -CUDART_INF_F;
    float l0 = 0.0f, l1 = 0.0f;     // per-thread partial (this quad lane's cols)

    const float4* kp4 = (const float4*)(g_k + (long long)plane * SS);
    const float4* vp4 = (const float4*)(g_v + (long long)plane * SS);
    const int ldc = tid & 15;       // float4 col 0..15  (dim = ldc*4)
    const int ldr = tid >> 4;       // 0..15

    for (int ch = 0; ch < NCH; ch++) {
        const int jbase = t0 - WW + ch * KC;
        if (jbase + KC <= 0 || jbase >= TT) continue;   // block-uniform skip

        // cooperative K/V load (zero-fill out-of-range keys)
#pragma unroll
        for (int it = 0; it < 4; it++) {
            int key = ldr + 16 * it;
            int j = jbase + key;
            bool v = (j >= 0) && (j < TT);
            float4 zero = make_float4(0.f, 0.f, 0.f, 0.f);
            float4 kv = v ? kp4[j * 16 + ldc] : zero;
            float4 vv = v ? vp4[j * 16 + ldc] : zero;
            *(float4*)&Ks[key][ldc * 4] = kv;
            *(float4*)&Vs[key][ldc * 4] = vv;
        }
        __syncthreads();

        // S = Q K^T  (16 x 64 per warp)
        float sacc[8][4];
#pragma unroll
        for (int nt = 0; nt < 8; nt++) {
#pragma unroll
            for (int i = 0; i < 4; i++) sacc[nt][i] = 0.0f;
#pragma unroll
            for (int kk = 0; kk < 8; kk++) {
                uint32_t bb[2];
                bb[0] = __float_as_uint(Ks[nt * 8 + qr][kk * 8 + qc    ]);
                bb[1] = __float_as_uint(Ks[nt * 8 + qr][kk * 8 + qc + 4]);
                mma_tf32(sacc[nt], qa[kk], bb);
            }
        }

        // mask (band + range) and row max
        float rmax0 = -CUDART_INF_F, rmax1 = -CUDART_INF_F;
#pragma unroll
        for (int nt = 0; nt < 8; nt++) {
            int j0 = jbase + nt * 8 + qc * 2;
            int j1 = j0 + 1;
            bool v00 = (j0 >= 0) && (j0 < TT) && (j0 >= tq0 - WW) && (j0 <= tq0 + WW);
            bool v01 = (j1 >= 0) && (j1 < TT) && (j1 >= tq0 - WW) && (j1 <= tq0 + WW);
            bool v10 = (j0 >= 0) && (j0 < TT) && (j0 >= tq1 - WW) && (j0 <= tq1 + WW);
            bool v11 = (j1 >= 0) && (j1 < TT) && (j1 >= tq1 - WW) && (j1 <= tq1 + WW);
            sacc[nt][0] = v00 ? sacc[nt][0] : -CUDART_INF_F;
            sacc[nt][1] = v01 ? sacc[nt][1] : -CUDART_INF_F;
            sacc[nt][2] = v10 ? sacc[nt][2] : -CUDART_INF_F;
            sacc[nt][3] = v11 ? sacc[nt][3] : -CUDART_INF_F;
            rmax0 = fmaxf(rmax0, fmaxf(sacc[nt][0], sacc[nt][1]));
            rmax1 = fmaxf(rmax1, fmaxf(sacc[nt][2], sacc[nt][3]));
        }
        rmax0 = fmaxf(rmax0, __shfl_xor_sync(0xFFFFFFFF, rmax0, 1));
        rmax0 = fmaxf(rmax0, __shfl_xor_sync(0xFFFFFFFF, rmax0, 2));
        rmax1 = fmaxf(rmax1, __shfl_xor_sync(0xFFFFFFFF, rmax1, 1));
        rmax1 = fmaxf(rmax1, __shfl_xor_sync(0xFFFFFFFF, rmax1, 2));

        // online softmax update (NaN-safe for fully-masked rows)
        float mn0 = fmaxf(mr0, rmax0);
        float mn1 = fmaxf(mr1, rmax1);
        bool live0 = (mn0 != -CUDART_INF_F);
        bool live1 = (mn1 != -CUDART_INF_F);
        float alpha0 = live0 ? __expf(mr0 - mn0) : 1.0f;
        float alpha1 = live1 ? __expf(mr1 - mn1) : 1.0f;
        if (live0) mr0 = mn0;
        if (live1) mr1 = mn1;
        l0 *= alpha0;
        l1 *= alpha1;
#pragma unroll
        for (int nt = 0; nt < 8; nt++) {
            oa[nt][0] *= alpha0; oa[nt][1] *= alpha0;
            oa[nt][2] *= alpha1; oa[nt][3] *= alpha1;
        }

        // PV, time-multiplexed: S n-tile kk == PV key-group kk.
        // For each kk: p = exp(s - m), stage 16x8 P slice, reload as A-frag, mma.
#pragma unroll
        for (int kk = 0; kk < 8; kk++) {
            float p0 = live0 ? __expf(sacc[kk][0] - mr0) : 0.0f;
            float p1 = live0 ? __expf(sacc[kk][1] - mr0) : 0.0f;
            float p2 = live1 ? __expf(sacc[kk][2] - mr1) : 0.0f;
            float p3 = live1 ? __expf(sacc[kk][3] - mr1) : 0.0f;
            l0 += p0 + p1;
            l1 += p2 + p3;

            __syncwarp();   // previous iteration's reads done before overwrite
            float2 w0; w0.x = f2tf32f(p0); w0.y = f2tf32f(p1);
            float2 w1; w1.x = f2tf32f(p2); w1.y = f2tf32f(p3);
            *(float2*)&Pb[wid][qr    ][qc * 2] = w0;
            *(float2*)&Pb[wid][qr + 8][qc * 2] = w1;
            __syncwarp();

            uint32_t pa[4];
            pa[0] = __float_as_uint(Pb[wid][qr    ][qc    ]);
            pa[1] = __float_as_uint(Pb[wid][qr + 8][qc    ]);
            pa[2] = __float_as_uint(Pb[wid][qr    ][qc + 4]);
            pa[3] = __float_as_uint(Pb[wid][qr + 8][qc + 4]);
#pragma unroll
            for (int nt = 0; nt < 8; nt++) {
                uint32_t bb[2];
                bb[0] = __float_as_uint(Vs[kk * 8 + qc    ][nt * 8 + qr]);
                bb[1] = __float_as_uint(Vs[kk * 8 + qc + 4][nt * 8 + qr]);
                mma_tf32(oa[nt], pa, bb);
            }
        }
        __syncthreads();   // before next chunk overwrites Ks/Vs
    }

    // l is a per-thread partial over this lane's key-columns; full row
    // denominator = sum over the quad (qc = 0..3).
    l0 += __shfl_xor_sync(0xFFFFFFFF, l0, 1);
    l0 += __shfl_xor_sync(0xFFFFFFFF, l0, 2);
    l1 += __shfl_xor_sync(0xFFFFFFFF, l1, 1);
    l1 += __shfl_xor_sync(0xFFFFFFFF, l1, 2);

    // normalize and write out [b, t, h*64+dim]
    const float inv0 = 1.0f / l0;   // own key always valid -> l > 0
    const float inv1 = 1.0f / l1;
    float* o0 = out + (((long long)b * TT + tq0) * HH + h) * SS;
    float* o1 = out + (((long long)b * TT + tq1) * HH + h) * SS;
#pragma unroll
    for (int nt = 0; nt < 8; nt++) {
        int dim = nt * 8 + qc * 2;
        float2 r0; r0.x = oa[nt][0] * inv0; r0.y = oa[nt][1] * inv0;
        float2 r1; r1.x = oa[nt][2] * inv1; r1.y = oa[nt][3] * inv1;
        *(float2*)&o0[dim] = r0;
        *(float2*)&o1[dim] = r1;
    }
}

// ---------------------------------------------------------------------------
// Launcher (graph-capturable: kernel launches only, no allocs, no syncs)
// ---------------------------------------------------------------------------
extern "C" void kernel_launch(void* const* d_in, const int* in_sizes, int n_in,
                              void* d_out, int out_size)
{
    const float* x  = (const float*)d_in[0];
    const float* Wq = (const float*)d_in[1];
    const float* Wk = (const float*)d_in[2];
    const float* Wv = (const float*)d_in[3];
    float* out = (float*)d_out;

    dim3 g1(MM / 128, EE / 64, 3);   // (64, 12, 3)
    qkv_gemm_tc<<<g1, 256>>>(x, Wq, Wk, Wv);

    dim3 g2(TT / QB, HH, BB);        // (32, 12, 2)
    banded_attn_tc<<<g2, 256>>>(out);
}

// round 13
// speedup vs baseline: 6.3623x; 1.0047x over previous
#include <cuda_runtime.h>
#include <math_constants.h>
#include <cstdint>

// Problem constants
#define BB 2
#define TT 4096
#define EE 768
#define HH 12
#define SS 64            // head dim
#define WW 256           // one-sided window
#define MM (BB*TT)       // 8192 rows in projection GEMM

// Scratch for projections, head-major layout [B, H, T, S], tf32-rounded floats
__device__ float g_q[BB*HH*TT*SS];
__device__ float g_k[BB*HH*TT*SS];
__device__ float g_v[BB*HH*TT*SS];

// ---------------------------------------------------------------------------
// tf32 + cp.async helpers
// ---------------------------------------------------------------------------
__device__ __forceinline__ uint32_t f2tf32(float f) {
    uint32_t u;
    asm("cvt.rna.tf32.f32 %0, %1;" : "=r"(u) : "f"(f));
    return u;
}
__device__ __forceinline__ float f2tf32f(float f) {
    return __uint_as_float(f2tf32(f));
}
__device__ __forceinline__ void cp16(uint32_t dst, const void* src) {
    asm volatile("cp.async.cg.shared.global [%0], [%1], 16;" :: "r"(dst), "l"(src));
}
__device__ __forceinline__ void cp_commit() { asm volatile("cp.async.commit_group;"); }
__device__ __forceinline__ void cp_wait0()  { asm volatile("cp.async.wait_group 0;"); }

// mma.sync m16n8k8 tf32, row.col, fp32 accumulate (in-place C)
__device__ __forceinline__ void mma_tf32(float* c, const uint32_t* a, const uint32_t* b) {
    asm volatile(
        "mma.sync.aligned.m16n8k8.row.col.f32.tf32.tf32.f32 "
        "{%0,%1,%2,%3}, {%4,%5,%6,%7}, {%8,%9}, {%0,%1,%2,%3};"
        : "+f"(c[0]), "+f"(c[1]), "+f"(c[2]), "+f"(c[3])
        : "r"(a[0]), "r"(a[1]), "r"(a[2]), "r"(a[3]), "r"(b[0]), "r"(b[1]));
}

// Fragment layouts (m16n8k8 tf32):
//  A (16x8):  a0=(r, c)  a1=(r+8, c)  a2=(r, c+4)  a3=(r+8, c+4)   r=lane/4, c=lane%4
//  B (8x8):   b0=(k, n)  b1=(k+4, n)                               k=lane%4, n=lane/4
//  C (16x8):  c0=(r,2c) c1=(r,2c+1) c2=(r+8,2c) c3=(r+8,2c+1)

// ---------------------------------------------------------------------------
// Kernel 1: QKV projection GEMM on tensor cores (tf32), cp.async 2-stage pipe.
// y[m,n] = sum_k x[m,k] * W[n,k]
// BM=128, BN=64(=head), BK=16, 256 threads = 8 warps (4M x 2N), warp tile 32x32.
// Raw fp32 staged via cp.async; tf32 rna conversion at fragment load.
// ld=20 floats: frag addr = row*20 + kb -> banks (20*qr+qc)%32, all 32 distinct.
// Row stride 80 bytes -> 16B-aligned for cp.async.
// ---------------------------------------------------------------------------
#define GBK 16
#define GNK (EE/GBK)    // 48

__global__ __launch_bounds__(256) void qkv_gemm_tc(
    const float* __restrict__ x,
    const float* __restrict__ Wq,
    const float* __restrict__ Wk,
    const float* __restrict__ Wv)
{
    const int z = blockIdx.z;
    const float* __restrict__ W = (z == 0) ? Wq : (z == 1) ? Wk : Wv;
    float* __restrict__ outp    = (z == 0) ? g_q : (z == 1) ? g_k : g_v;
    const float scale = (z == 0) ? 0.125f : 1.0f;

    __shared__ float Xs[2][128][20];
    __shared__ float Ws[2][64][20];

    const int tid  = threadIdx.x;
    const int wid  = tid >> 5;
    const int lane = tid & 31;
    const int warpM = wid >> 1;     // 0..3
    const int warpN = wid & 1;      // 0..1
    const int m0 = blockIdx.x * 128;
    const int h  = blockIdx.y;      // head == BN block
    const int n0 = h * 64;

    const uint32_t xs_base = (uint32_t)__cvta_generic_to_shared(&Xs[0][0][0]);
    const uint32_t ws_base = (uint32_t)__cvta_generic_to_shared(&Ws[0][0][0]);

    float acc[2][4][4];
#pragma unroll
    for (int mt = 0; mt < 2; mt++)
#pragma unroll
        for (int nt = 0; nt < 4; nt++)
#pragma unroll
            for (int i = 0; i < 4; i++) acc[mt][nt][i] = 0.0f;

    // per-thread load slots
    const int xr0 = tid >> 2;            // 0..63   (two row groups: +0, +64)
    const int xc4 = tid & 3;             // float4 col 0..3
    const int wr  = tid >> 2;            // 0..63
    const int wc4 = tid & 3;

    auto load_stage = [&](int s, int k0) {
        // X tile: 128 x 16 (2 float4 per thread)
        cp16(xs_base + (((s * 128 + xr0     ) * 20) + xc4 * 4) * 4,
             &x[(m0 + xr0     ) * EE + k0 + xc4 * 4]);
        cp16(xs_base + (((s * 128 + xr0 + 64) * 20) + xc4 * 4) * 4,
             &x[(m0 + xr0 + 64) * EE + k0 + xc4 * 4]);
        // W tile: 64 x 16 (1 float4 per thread)
        cp16(ws_base + (((s * 64 + wr) * 20) + wc4 * 4) * 4,
             &W[(n0 + wr) * EE + k0 + wc4 * 4]);
    };

    load_stage(0, 0);
    cp_commit();

    for (int i = 0; i < GNK; i++) {
        cp_wait0();
        __syncthreads();
        if (i + 1 < GNK) {
            load_stage((i + 1) & 1, (i + 1) * GBK);
        }
        cp_commit();

        const int s = i & 1;
#pragma unroll
        for (int kk = 0; kk < 2; kk++) {
            const int kb = kk * 8 + (lane & 3);
            uint32_t a[2][4];
#pragma unroll
            for (int mt = 0; mt < 2; mt++) {
                int row = warpM * 32 + mt * 16 + (lane >> 2);
                a[mt][0] = f2tf32(Xs[s][row    ][kb    ]);
                a[mt][1] = f2tf32(Xs[s][row + 8][kb    ]);
                a[mt][2] = f2tf32(Xs[s][row    ][kb + 4]);
                a[mt][3] = f2tf32(Xs[s][row + 8][kb + 4]);
            }
            uint32_t b[4][2];
#pragma unroll
            for (int nt = 0; nt < 4; nt++) {
                int col = warpN * 32 + nt * 8 + (lane >> 2);
                b[nt][0] = f2tf32(Ws[s][col][kb    ]);
                b[nt][1] = f2tf32(Ws[s][col][kb + 4]);
            }
#pragma unroll
            for (int mt = 0; mt < 2; mt++)
#pragma unroll
                for (int nt = 0; nt < 4; nt++)
                    mma_tf32(acc[mt][nt], a[mt], b[nt]);
        }
        __syncthreads();   // all warps done with stage s before refill in i+2
    }

    // epilogue: scale, round to tf32, store head-major [B,H,T,S]
#pragma unroll
    for (int mt = 0; mt < 2; mt++) {
        int m = m0 + warpM * 32 + mt * 16 + (lane >> 2);
#pragma unroll
        for (int half = 0; half < 2; half++) {
            int mm = m + half * 8;
            int bI = mm >> 12;
            int t  = mm & (TT - 1);
            float* rowp = outp + ((bI * HH + h) * TT + t) * SS;
#pragma unroll
            for (int nt = 0; nt < 4; nt++) {
                int col = warpN * 32 + nt * 8 + (lane & 3) * 2;
                float2 o;
                o.x = f2tf32f(acc[mt][nt][half * 2 + 0] * scale);
                o.y = f2tf32f(acc[mt][nt][half * 2 + 1] * scale);
                *(float2*)&rowp[col] = o;
            }
        }
    }
}

// ---------------------------------------------------------------------------
// Kernel 2: banded attention on tensor cores, flash-style online softmax.
// R12: CTA = 64 queries / 128 threads (4 warps). 145 regs/thread -> 3 CTAs/SM
// (12 warps) vs 8 before, and band waste drops (576 keys streamed per 64
// queries vs 640 per 128). Each warp owns 16 query rows (one m16 tile).
// K/V ld: 68 (K) / 72 (V) -> B-frag reads hit all 32 banks.
// ---------------------------------------------------------------------------
#define QB 64
#define KC 64
#define NCH ((2*WW + QB)/KC)   // 9
#define ATH 128                // attention CTA threads

__global__ __launch_bounds__(ATH, 1) void banded_attn_tc(float* __restrict__ out)
{
    __shared__ float Ks[KC][68];       // [key][dim 0..63]
    __shared__ float Vs[KC][72];       // [key][dim 0..63]
    __shared__ float Pb[4][16][12];    // per-warp P slice [qrow][key-in-group]

    const int tid  = threadIdx.x;
    const int wid  = tid >> 5;          // 0..3
    const int lane = tid & 31;
    const int t0 = blockIdx.x * QB;
    const int h  = blockIdx.y;
    const int b  = blockIdx.z;
    const int plane = (b * HH + h) * TT;

    const int qr = (lane >> 2);             // 0..7
    const int qc = (lane & 3);              // 0..3
    const int tq0 = t0 + wid * 16 + qr;     // this thread's query row 0
    const int tq1 = tq0 + 8;                //                  ... row 1

    // persistent Q fragments (already tf32-rounded & scaled by GEMM epilogue)
    uint32_t qa[8][4];
#pragma unroll
    for (int kk = 0; kk < 8; kk++) {
        const float* q0 = g_q + (plane + tq0) * SS + kk * 8 + qc;
        const float* q1 = g_q + (plane + tq1) * SS + kk * 8 + qc;
        qa[kk][0] = __float_as_uint(q0[0]);
        qa[kk][1] = __float_as_uint(q1[0]);
        qa[kk][2] = __float_as_uint(q0[4]);
        qa[kk][3] = __float_as_uint(q1[4]);
    }

    float oa[8][4];
#pragma unroll
    for (int nt = 0; nt < 8; nt++)
#pragma unroll
        for (int i = 0; i < 4; i++) oa[nt][i] = 0.0f;

    float mr0 = -CUDART_INF_F, mr1 = -CUDART_INF_F;
    float l0 = 0.0f, l1 = 0.0f;     // per-thread partial (this quad lane's cols)

    const float4* kp4 = (const float4*)(g_k + (long long)plane * SS);
    const float4* vp4 = (const float4*)(g_v + (long long)plane * SS);
    const int ldc = tid & 15;       // float4 col 0..15  (dim = ldc*4)
    const int ldr = tid >> 4;       // 0..7

    for (int ch = 0; ch < NCH; ch++) {
        const int jbase = t0 - WW + ch * KC;
        if (jbase + KC <= 0 || jbase >= TT) continue;   // block-uniform skip

        // cooperative K/V load (zero-fill out-of-range keys): 64x16 float4 each
#pragma unroll
        for (int it = 0; it < 8; it++) {
            int key = ldr + 8 * it;
            int j = jbase + key;
            bool v = (j >= 0) && (j < TT);
            float4 zero = make_float4(0.f, 0.f, 0.f, 0.f);
            float4 kv = v ? kp4[j * 16 + ldc] : zero;
            float4 vv = v ? vp4[j * 16 + ldc] : zero;
            *(float4*)&Ks[key][ldc * 4] = kv;
            *(float4*)&Vs[key][ldc * 4] = vv;
        }
        __syncthreads();

        // S = Q K^T  (16 x 64 per warp)
        float sacc[8][4];
#pragma unroll
        for (int nt = 0; nt < 8; nt++) {
#pragma unroll
            for (int i = 0; i < 4; i++) sacc[nt][i] = 0.0f;
#pragma unroll
            for (int kk = 0; kk < 8; kk++) {
                uint32_t bb[2];
                bb[0] = __float_as_uint(Ks[nt * 8 + qr][kk * 8 + qc    ]);
                bb[1] = __float_as_uint(Ks[nt * 8 + qr][kk * 8 + qc + 4]);
                mma_tf32(sacc[nt], qa[kk], bb);
            }
        }

        // mask (band + range) and row max
        float rmax0 = -CUDART_INF_F, rmax1 = -CUDART_INF_F;
#pragma unroll
        for (int nt = 0; nt < 8; nt++) {
            int j0 = jbase + nt * 8 + qc * 2;
            int j1 = j0 + 1;
            bool v00 = (j0 >= 0) && (j0 < TT) && (j0 >= tq0 - WW) && (j0 <= tq0 + WW);
            bool v01 = (j1 >= 0) && (j1 < TT) && (j1 >= tq0 - WW) && (j1 <= tq0 + WW);
            bool v10 = (j0 >= 0) && (j0 < TT) && (j0 >= tq1 - WW) && (j0 <= tq1 + WW);
            bool v11 = (j1 >= 0) && (j1 < TT) && (j1 >= tq1 - WW) && (j1 <= tq1 + WW);
            sacc[nt][0] = v00 ? sacc[nt][0] : -CUDART_INF_F;
            sacc[nt][1] = v01 ? sacc[nt][1] : -CUDART_INF_F;
            sacc[nt][2] = v10 ? sacc[nt][2] : -CUDART_INF_F;
            sacc[nt][3] = v11 ? sacc[nt][3] : -CUDART_INF_F;
            rmax0 = fmaxf(rmax0, fmaxf(sacc[nt][0], sacc[nt][1]));
            rmax1 = fmaxf(rmax1, fmaxf(sacc[nt][2], sacc[nt][3]));
        }
        rmax0 = fmaxf(rmax0, __shfl_xor_sync(0xFFFFFFFF, rmax0, 1));
        rmax0 = fmaxf(rmax0, __shfl_xor_sync(0xFFFFFFFF, rmax0, 2));
        rmax1 = fmaxf(rmax1, __shfl_xor_sync(0xFFFFFFFF, rmax1, 1));
        rmax1 = fmaxf(rmax1, __shfl_xor_sync(0xFFFFFFFF, rmax1, 2));

        // online softmax update (NaN-safe for fully-masked rows)
        float mn0 = fmaxf(mr0, rmax0);
        float mn1 = fmaxf(mr1, rmax1);
        bool live0 = (mn0 != -CUDART_INF_F);
        bool live1 = (mn1 != -CUDART_INF_F);
        float alpha0 = live0 ? __expf(mr0 - mn0) : 1.0f;
        float alpha1 = live1 ? __expf(mr1 - mn1) : 1.0f;
        if (live0) mr0 = mn0;
        if (live1) mr1 = mn1;
        l0 *= alpha0;
        l1 *= alpha1;
#pragma unroll
        for (int nt = 0; nt < 8; nt++) {
            oa[nt][0] *= alpha0; oa[nt][1] *= alpha0;
            oa[nt][2] *= alpha1; oa[nt][3] *= alpha1;
        }

        // PV, time-multiplexed: S n-tile kk == PV key-group kk.
#pragma unroll
        for (int kk = 0; kk < 8; kk++) {
            float p0 = live0 ? __expf(sacc[kk][0] - mr0) : 0.0f;
            float p1 = live0 ? __expf(sacc[kk][1] - mr0) : 0.0f;
            float p2 = live1 ? __expf(sacc[kk][2] - mr1) : 0.0f;
            float p3 = live1 ? __expf(sacc[kk][3] - mr1) : 0.0f;
            l0 += p0 + p1;
            l1 += p2 + p3;

            __syncwarp();   // previous iteration's reads done before overwrite
            float2 w0; w0.x = f2tf32f(p0); w0.y = f2tf32f(p1);
            float2 w1; w1.x = f2tf32f(p2); w1.y = f2tf32f(p3);
            *(float2*)&Pb[wid][qr    ][qc * 2] = w0;
            *(float2*)&Pb[wid][qr + 8][qc * 2] = w1;
            __syncwarp();

            uint32_t pa[4];
            pa[0] = __float_as_uint(Pb[wid][qr    ][qc    ]);
            pa[1] = __float_as_uint(Pb[wid][qr + 8][qc    ]);
            pa[2] = __float_as_uint(Pb[wid][qr    ][qc + 4]);
            pa[3] = __float_as_uint(Pb[wid][qr + 8][qc + 4]);
#pragma unroll
            for (int nt = 0; nt < 8; nt++) {
                uint32_t bb[2];
                bb[0] = __float_as_uint(Vs[kk * 8 + qc    ][nt * 8 + qr]);
                bb[1] = __float_as_uint(Vs[kk * 8 + qc + 4][nt * 8 + qr]);
                mma_tf32(oa[nt], pa, bb);
            }
        }
        __syncthreads();   // before next chunk overwrites Ks/Vs
    }

    // l is a per-thread partial over this lane's key-columns; full row
    // denominator = sum over the quad (qc = 0..3).
    l0 += __shfl_xor_sync(0xFFFFFFFF, l0, 1);
    l0 += __shfl_xor_sync(0xFFFFFFFF, l0, 2);
    l1 += __shfl_xor_sync(0xFFFFFFFF, l1, 1);
    l1 += __shfl_xor_sync(0xFFFFFFFF, l1, 2);

    // normalize and write out [b, t, h*64+dim]
    const float inv0 = 1.0f / l0;   // own key always valid -> l > 0
    const float inv1 = 1.0f / l1;
    float* o0 = out + (((long long)b * TT + tq0) * HH + h) * SS;
    float* o1 = out + (((long long)b * TT + tq1) * HH + h) * SS;
#pragma unroll
    for (int nt = 0; nt < 8; nt++) {
        int dim = nt * 8 + qc * 2;
        float2 r0; r0.x = oa[nt][0] * inv0; r0.y = oa[nt][1] * inv0;
        float2 r1; r1.x = oa[nt][2] * inv1; r1.y = oa[nt][3] * inv1;
        *(float2*)&o0[dim] = r0;
        *(float2*)&o1[dim] = r1;
    }
}

// ---------------------------------------------------------------------------
// Launcher (graph-capturable: kernel launches only, no allocs, no syncs)
// ---------------------------------------------------------------------------
extern "C" void kernel_launch(void* const* d_in, const int* in_sizes, int n_in,
                              void* d_out, int out_size)
{
    const float* x  = (const float*)d_in[0];
    const float* Wq = (const float*)d_in[1];
    const float* Wk = (const float*)d_in[2];
    const float* Wv = (const float*)d_in[3];
    float* out = (float*)d_out;

    dim3 g1(MM / 128, EE / 64, 3);   // (64, 12, 3)
    qkv_gemm_tc<<<g1, 256>>>(x, Wq, Wk, Wv);

    dim3 g2(TT / QB, HH, BB);        // (64, 12, 2)
    banded_attn_tc<<<g2, ATH>>>(out);
}